// round 2
// baseline (speedup 1.0000x reference)
#include <cuda_runtime.h>
#include <math.h>

#define BATCH 512
#define LEN   50
#define EMB   512
#define C1    20
#define C2    40
#define EPSV  1e-5f

// ---------------- device scratch (no allocations allowed) ----------------
__device__ float g_max [2*BATCH*C1*25];   // smax (side0) / tmax (side1): [side][b][c][x]
__device__ float g_A   [2*BATCH*C2*23];   // A (side0) / B (side1): [side][b][o][x]
__device__ float g_s1  [2*BATCH*C2];      // per-sample sums
__device__ float g_s2  [2*BATCH*C2];      // per-sample sums of squares
__device__ float g_Wxy [2*C2*C1*3];       // Wx | Wy
__device__ float g_bn2 [2*C2];            // scale | shift
__device__ float g_P2  [BATCH*4840];      // flattened pooled2, matches Wfc1 layout
__device__ float g_part[40*BATCH*C1];     // FC1 K-split partials [ks][b][c]

// ---------------------------------------------------------------------------
// Kernel 1: embedding gather + proj GEMM + per-sample BN1 + relu + pairwise max
// block = one sample PAIR, both sides = 200 token rows. 256 threads.
// f[t][c] = dot(emb[tok[t]], W1[c])   (b1 cancels inside BN1)
// ---------------------------------------------------------------------------
__global__ __launch_bounds__(256, 2)
void k1(const int* __restrict__ src, const int* __restrict__ trg,
        const float* __restrict__ emb_src, const float* __restrict__ emb_trg,
        const float* __restrict__ W1,
        const float* __restrict__ g1, const float* __restrict__ beta1)
{
    extern __shared__ float sm[];
    float* es  = sm;                    // [64][208]  e-chunk, transposed: es[jj][t]
    float* ws  = es + 64*208;           // [64][20]   w-chunk: ws[jj][c]
    float* fs  = ws + 64*20;            // [200][21]  f results (padded)
    int*   tok = (int*)(fs + 200*21);   // [200]
    float* bnS = (float*)(tok + 200);   // [80] scale per (unit,c)
    float* bnH = bnS + 80;              // [80] shift per (unit,c)

    const int tid = threadIdx.x;
    const int bp  = blockIdx.x;         // sample pair index

    if (tid < 200) {
        int u = tid / 50, l = tid % 50;
        int side = u >> 1;
        int b = bp*2 + (u & 1);
        tok[tid] = (side ? trg : src)[b*LEN + l];
    }
    __syncthreads();

    float acc[20];
#pragma unroll
    for (int i = 0; i < 20; i++) acc[i] = 0.f;

    const int tg = tid >> 2;            // token group (4 tokens)
    const int cg = tid & 3;             // channel group (c = cg + 4u)
    const int t0 = tg * 4;
    const bool active = (tid < 200);

    for (int ck = 0; ck < 8; ck++) {
        // stage 200 token-rows x 64 floats, transposed
        for (int q = tid; q < 3200; q += 256) {
            int t = q >> 4, j4 = q & 15;
            int side = t / 100;
            const float* base = side ? emb_trg : emb_src;
            float4 v = *(const float4*)(base + (size_t)tok[t]*EMB + ck*64 + j4*4);
            int jj = j4*4;
            es[(jj+0)*208 + t] = v.x;
            es[(jj+1)*208 + t] = v.y;
            es[(jj+2)*208 + t] = v.z;
            es[(jj+3)*208 + t] = v.w;
        }
        for (int q = tid; q < 1280; q += 256) {
            int c = q >> 6, jj = q & 63;
            ws[jj*20 + c] = W1[c*EMB + ck*64 + jj];
        }
        __syncthreads();

        if (active) {
#pragma unroll 4
            for (int jj = 0; jj < 64; jj++) {
                float4 e = *(const float4*)&es[jj*208 + t0];
#pragma unroll
                for (int u = 0; u < 5; u++) {
                    float w = ws[jj*20 + cg + 4*u];
                    acc[0*5+u] += e.x * w;
                    acc[1*5+u] += e.y * w;
                    acc[2*5+u] += e.z * w;
                    acc[3*5+u] += e.w * w;
                }
            }
        }
        __syncthreads();
    }

    if (active) {
#pragma unroll
        for (int i = 0; i < 4; i++)
#pragma unroll
            for (int u = 0; u < 5; u++)
                fs[(t0+i)*21 + cg + 4*u] = acc[i*5+u];
    }
    __syncthreads();

    // BN1 stats: per (unit, channel) over the 50 positions (biased var)
    if (tid < 80) {
        int u = tid / 20, c = tid % 20;
        float s = 0.f, s2 = 0.f;
        for (int l = 0; l < 50; l++) {
            float v = fs[(u*50 + l)*21 + c];
            s += v; s2 += v*v;
        }
        float mu  = s * (1.f/50.f);
        float var = s2 * (1.f/50.f) - mu*mu;
        float sc  = g1[c] * rsqrtf(var + EPSV);
        bnS[tid] = sc;
        bnH[tid] = beta1[c] - mu*sc;
    }
    __syncthreads();

    // apply BN + relu + pairwise max (the first maxpool, separated)
    for (int q = tid; q < 2000; q += 256) {
        int u = q / 500, r = q % 500;
        int c = r / 25, x = r % 25;
        float sc = bnS[u*20+c], sh = bnH[u*20+c];
        float a0 = fs[(u*50 + 2*x  )*21 + c]*sc + sh;
        float a1 = fs[(u*50 + 2*x+1)*21 + c]*sc + sh;
        int side = u >> 1;
        int b = bp*2 + (u & 1);
        g_max[((side*BATCH + b)*C1 + c)*25 + x] = fmaxf(fmaxf(a0, a1), 0.f);
    }
}

// ---------------------------------------------------------------------------
// Wx[o,c,dx] = sum_dy W2 ; Wy[o,c,dy] = sum_dx W2
// ---------------------------------------------------------------------------
__global__ void k_wxy(const float* __restrict__ W2)
{
    for (int q = threadIdx.x; q < C2*C1*3; q += blockDim.x) {
        int o = q / (C1*3), r = q % (C1*3), c = r / 3, d = r % 3;
        const float* w = W2 + ((o*C1 + c)*3)*3;
        g_Wxy[q]           = w[0*3+d] + w[1*3+d] + w[2*3+d];  // Wx
        g_Wxy[C2*C1*3 + q] = w[d*3+0] + w[d*3+1] + w[d*3+2];  // Wy
    }
}

// ---------------------------------------------------------------------------
// Kernel 2: 1-D convs A[b,o,x] / B[b,o,y] + per-sample sums for BN2 stats
// ---------------------------------------------------------------------------
__global__ void k2()
{
    __shared__ float m_s[C1*25];
    __shared__ float w_s[C2*C1*3];
    __shared__ float a_s[C2*23];
    const int b = blockIdx.x, side = blockIdx.y, tid = threadIdx.x;

    for (int q = tid; q < C1*25; q += 256)  m_s[q] = g_max[(size_t)(side*BATCH + b)*C1*25 + q];
    for (int q = tid; q < C2*C1*3; q += 256) w_s[q] = g_Wxy[side*C2*C1*3 + q];
    __syncthreads();

    for (int q = tid; q < C2*23; q += 256) {
        int o = q / 23, x = q % 23;
        float acc = 0.f;
#pragma unroll
        for (int c = 0; c < C1; c++) {
            const float* w = &w_s[(o*C1 + c)*3];
            const float* m = &m_s[c*25 + x];
            acc += w[0]*m[0] + w[1]*m[1] + w[2]*m[2];
        }
        a_s[q] = acc;
        g_A[(size_t)(side*BATCH + b)*C2*23 + q] = acc;
    }
    __syncthreads();

    if (tid < C2) {
        float s = 0.f, s2 = 0.f;
        for (int x = 0; x < 23; x++) { float v = a_s[tid*23 + x]; s += v; s2 += v*v; }
        g_s1[(size_t)(side*BATCH + b)*C2 + tid] = s;
        g_s2[(size_t)(side*BATCH + b)*C2 + tid] = s2;
    }
}

// ---------------------------------------------------------------------------
// Kernel 3: BN2 global stats from per-sample 1-D sums (b2 cancels)
// ---------------------------------------------------------------------------
__global__ void k3(const float* __restrict__ g2, const float* __restrict__ beta2)
{
    __shared__ double rS[256], rQ[256];
    const int o = blockIdx.x, tid = threadIdx.x;
    double aS = 0.0, aQ = 0.0;
    for (int b = tid; b < BATCH; b += 256) {
        double sA = g_s1[b*C2 + o],            sB = g_s1[(BATCH + b)*C2 + o];
        double qA = g_s2[b*C2 + o],            qB = g_s2[(BATCH + b)*C2 + o];
        aS += 23.0*(sA + sB);
        aQ += 23.0*qA + 2.0*sA*sB + 23.0*qB;
    }
    rS[tid] = aS; rQ[tid] = aQ;
    __syncthreads();
    for (int s = 128; s > 0; s >>= 1) {
        if (tid < s) { rS[tid] += rS[tid+s]; rQ[tid] += rQ[tid+s]; }
        __syncthreads();
    }
    if (tid == 0) {
        double N    = (double)BATCH * 529.0;
        double mean = rS[0] / N;
        double var  = rQ[0] / N - mean*mean;
        float  sc   = g2[o] * (float)(1.0 / sqrt(var + (double)EPSV));
        g_bn2[o]      = sc;
        g_bn2[C2 + o] = beta2[o] - (float)mean * sc;
    }
}

// ---------------------------------------------------------------------------
// Kernel 4: BN2 apply + relu + maxpool2 (separated) -> P2[b][o*121+yy*11+xx]
// ---------------------------------------------------------------------------
__global__ void k4()
{
    __shared__ float As[C2*23], Bs[C2*23], ua[C2*11], vb[C2*11], sc_s[C2], sh_s[C2];
    const int b = blockIdx.x, tid = threadIdx.x;

    for (int q = tid; q < C2*23; q += 256) {
        As[q] = g_A[(size_t)b*C2*23 + q];
        Bs[q] = g_A[(size_t)(BATCH + b)*C2*23 + q];
    }
    if (tid < C2) { sc_s[tid] = g_bn2[tid]; sh_s[tid] = g_bn2[C2+tid]; }
    __syncthreads();

    for (int q = tid; q < 2*C2*11; q += 256) {
        int half = q / (C2*11), r = q % (C2*11);
        int o = r / 11, xx = r % 11;
        float sc = sc_s[o];
        const float* p = half ? &Bs[o*23] : &As[o*23];
        float v = fmaxf(sc*p[2*xx], sc*p[2*xx+1]);
        (half ? vb : ua)[r] = v;
    }
    __syncthreads();

    for (int q = tid; q < 4840; q += 256) {
        int o = q / 121, r = q % 121, yy = r / 11, xx = r % 11;
        g_P2[(size_t)b*4840 + q] = fmaxf(ua[o*11+xx] + vb[o*11+yy] + sh_s[o], 0.f);
    }
}

// ---------------------------------------------------------------------------
// Kernel 5: FC1 as K-split GEMM  [512,4840] @ [4840,20] -> partials[ks][b][c]
// grid (8 m-tiles, 40 k-splits of 121), 320 threads
// ---------------------------------------------------------------------------
__global__ __launch_bounds__(320)
void k5(const float* __restrict__ Wfc1)
{
    __shared__ __align__(16) float pT[121*68];  // transposed: pT[k][m]
    __shared__ float wf[20*124];
    const int mt = blockIdx.x, ks = blockIdx.y, tid = threadIdx.x;

    for (int q = tid; q < 64*121; q += 320) {
        int r = q / 121, k = q % 121;
        pT[k*68 + r] = g_P2[(size_t)(mt*64 + r)*4840 + ks*121 + k];
    }
    for (int q = tid; q < 20*121; q += 320) {
        int c = q / 121, k = q % 121;
        wf[c*124 + k] = Wfc1[c*4840 + ks*121 + k];
    }
    __syncthreads();

    const int mq = tid & 15, c = tid >> 4;   // 16 m-quads x 20 channels = 320
    float a0=0.f, a1=0.f, a2=0.f, a3=0.f;
#pragma unroll 4
    for (int k = 0; k < 121; k++) {
        float4 p = *(const float4*)&pT[k*68 + mq*4];
        float  w = wf[c*124 + k];
        a0 += p.x*w; a1 += p.y*w; a2 += p.z*w; a3 += p.w*w;
    }
    const int m = mt*64 + mq*4;
    float* dst = &g_part[((size_t)ks*BATCH + m)*C1 + c];
    dst[0] = a0; dst[C1] = a1; dst[2*C1] = a2; dst[3*C1] = a3;
}

// ---------------------------------------------------------------------------
// Kernel 6: reduce K-splits + FC2 + sigmoid
// ---------------------------------------------------------------------------
__global__ void k6(const float* __restrict__ bfc1, const float* __restrict__ Wfc2,
                   const float* __restrict__ bfc2, float* __restrict__ out)
{
    const int b = blockIdx.x*256 + threadIdx.x;
    if (b >= BATCH) return;
    float acc[C1];
#pragma unroll
    for (int c = 0; c < C1; c++) acc[c] = bfc1[c];
    for (int ks = 0; ks < 40; ks++) {
        const float* p = &g_part[((size_t)ks*BATCH + b)*C1];
#pragma unroll
        for (int c = 0; c < C1; c++) acc[c] += p[c];
    }
    float z = bfc2[0];
#pragma unroll
    for (int c = 0; c < C1; c++) z += Wfc2[c]*acc[c];
    out[b] = 1.f / (1.f + expf(-z));
}

// ---------------------------------------------------------------------------
extern "C" void kernel_launch(void* const* d_in, const int* in_sizes, int n_in,
                              void* d_out, int out_size)
{
    const int*   src     = (const int*)  d_in[0];
    const int*   trg     = (const int*)  d_in[1];
    // d_in[2] = pad_idx (unused by the reference)
    const float* emb_src = (const float*)d_in[3];
    const float* emb_trg = (const float*)d_in[4];
    const float* W1      = (const float*)d_in[5];
    // d_in[6] = b1 (cancels inside BN1)
    const float* g1      = (const float*)d_in[7];
    const float* beta1   = (const float*)d_in[8];
    const float* W2      = (const float*)d_in[9];
    // d_in[10] = b2 (cancels inside BN2)
    const float* g2      = (const float*)d_in[11];
    const float* beta2   = (const float*)d_in[12];
    const float* Wfc1    = (const float*)d_in[13];
    const float* bfc1    = (const float*)d_in[14];
    const float* Wfc2    = (const float*)d_in[15];
    const float* bfc2    = (const float*)d_in[16];

    const size_t sm1 = (size_t)(64*208 + 64*20 + 200*21)*4 + 200*4 + 160*4;
    cudaFuncSetAttribute(k1, cudaFuncAttributeMaxDynamicSharedMemorySize, (int)sm1);

    k1<<<BATCH/2, 256, sm1>>>(src, trg, emb_src, emb_trg, W1, g1, beta1);
    k_wxy<<<1, 256>>>(W2);
    k2<<<dim3(BATCH, 2), 256>>>();
    k3<<<C2, 256>>>(g2, beta2);
    k4<<<BATCH, 256>>>();
    k5<<<dim3(8, 40), 320>>>(Wfc1);
    k6<<<2, 256>>>(bfc1, Wfc2, bfc2, (float*)d_out);
}

// round 3
// speedup vs baseline: 1.8220x; 1.8220x over previous
#include <cuda_runtime.h>
#include <math.h>

#define BATCH 512
#define LEN   50
#define EMB   512
#define C1    20
#define C2    40
#define EPSV  1e-5f

// ---------------- device scratch ----------------
__device__ float g_A   [2*BATCH*C2*23];   // A (side0) / B (side1): [side][b][o][x]
__device__ float g_s1  [C2*2*BATCH];      // [o][side][b] per-sample sums (coalesced for k3)
__device__ float g_s2  [C2*2*BATCH];
__device__ float g_bn2 [2*C2];            // scale | shift
__device__ float g_weff[4840];            // Wfc2 @ Wfc1
__device__ float g_bias0;

// packed f32x2 fma (Blackwell FFMA2 — only reachable via PTX)
__device__ __forceinline__ void ffma2(unsigned long long& d,
                                      unsigned long long a, unsigned long long b) {
    asm("fma.rn.f32x2 %0, %1, %2, %0;" : "+l"(d) : "l"(a), "l"(b));
}
__device__ __forceinline__ float f2sum(unsigned long long v) {
    return __uint_as_float((unsigned)v) + __uint_as_float((unsigned)(v >> 32));
}

// smem byte offsets (dynamic)
#define ESR      208                       // float4 stride per j4 row
#define OFF_ES   0                         // float4 es[2][8*ESR]  = 53248 B
#define OFF_WS   53248                     // float4 ws[2][160]    =  5120 B
#define OFF_FS   58368                     // float  fs[200*21]    = 16800 B
#define OFF_TOK  75168                     // int    tok[200]      =   800 B
#define OFF_BN   75968                     // float  bn[160]       =   640 B
#define SMEM_K1  76608
// reuse of es region after GEMM:
#define OFF_WXY  0                         // float wxy[4800] = 19200 B
#define OFF_M    19200                     // float m[2000]   =  8000 B
#define OFF_AS   27200                     // float as_[3680] = 14720 B

// ---------------------------------------------------------------------------
// k1: gather + proj GEMM (FFMA2) + BN1 + relu + pool1 + conv1d + BN2 sums
// block = one sample PAIR (200 token rows), 256 threads, 2 blocks/SM
// ---------------------------------------------------------------------------
__global__ __launch_bounds__(256, 2)
void k1(const int* __restrict__ src, const int* __restrict__ trg,
        const float* __restrict__ emb_src, const float* __restrict__ emb_trg,
        const float* __restrict__ W1, const float* __restrict__ g1,
        const float* __restrict__ beta1, const float* __restrict__ W2)
{
    extern __shared__ char smraw[];
    float4* es  = (float4*)(smraw + OFF_ES);
    float4* ws  = (float4*)(smraw + OFF_WS);
    float*  fs  = (float* )(smraw + OFF_FS);
    int*    tok = (int*   )(smraw + OFF_TOK);
    float*  bn  = (float* )(smraw + OFF_BN);
    float*  wxy = (float* )(smraw + OFF_WXY);
    float*  m   = (float* )(smraw + OFF_M);
    float*  as_ = (float* )(smraw + OFF_AS);

    const int tid = threadIdx.x;
    const int bp  = blockIdx.x;

    if (tid < 200) {
        int u = tid / 50, l = tid % 50;
        int side = u >> 1;
        int b = bp*2 + (u & 1);
        tok[tid] = (side ? trg : src)[b*LEN + l];
    }
    __syncthreads();

    // stage one half-chunk (32 j = 8 j4) into buffer `buf`
    auto stage = [&](int h, int buf) {
        float4* eb = es + buf*(8*ESR);
        float4* wb = ws + buf*160;
#pragma unroll
        for (int it = 0; it < 7; it++) {
            int q = tid + it*256;
            if (q < 1600) {
                int t = q >> 3, j4 = q & 7;
                const float* base = (t >= 100) ? emb_trg : emb_src;
                float4 v = *(const float4*)(base + (size_t)tok[t]*EMB + h*32 + j4*4);
                eb[j4*ESR + t + j4] = v;          // rotated column: conflict-free
            }
        }
        if (tid < 160) {
            int c = tid >> 3, j4 = tid & 7;
            wb[c*8 + j4] = *(const float4*)(W1 + c*EMB + h*32 + j4*4);
        }
    };

    unsigned long long acc2[20];
#pragma unroll
    for (int c = 0; c < 20; c++) acc2[c] = 0ULL;

    const int t = tid;
    const bool active = (tid < 200);

    stage(0, 0);
    __syncthreads();
    for (int h = 0; h < 16; h++) {
        int buf = h & 1;
        if (h < 15) stage(h + 1, buf ^ 1);
        if (active) {
            const float4* eb = es + buf*(8*ESR);
            const float4* wb = ws + buf*160;
#pragma unroll
            for (int j4 = 0; j4 < 8; j4++) {
                ulonglong2 e = *(const ulonglong2*)&eb[j4*ESR + t + j4];
#pragma unroll
                for (int c = 0; c < 20; c++) {
                    ulonglong2 w = *(const ulonglong2*)&wb[c*8 + j4];
                    ffma2(acc2[c], e.x, w.x);
                    ffma2(acc2[c], e.y, w.y);
                }
            }
        }
        __syncthreads();
    }

    if (active) {
#pragma unroll
        for (int c = 0; c < 20; c++) fs[t*21 + c] = f2sum(acc2[c]);
    }
    __syncthreads();

    // BN1 stats (tid<80) in parallel with Wxy/Wy precompute (all threads; reuses es)
    if (tid < 80) {
        int u = tid / 20, c = tid % 20;
        float s = 0.f, s2 = 0.f;
#pragma unroll 10
        for (int l = 0; l < 50; l++) {
            float v = fs[(u*50 + l)*21 + c];
            s += v; s2 += v*v;
        }
        float mu  = s * (1.f/50.f);
        float var = s2 * (1.f/50.f) - mu*mu;
        float sc  = g1[c] * rsqrtf(var + EPSV);
        bn[tid]      = sc;
        bn[80 + tid] = beta1[c] - mu*sc;
    }
    for (int q = tid; q < 4800; q += 256) {
        int sside = q / 2400, r = q % 2400;
        int o = r / 60, rc = r % 60, c = rc / 3, d = rc % 3;
        const float* w = W2 + (o*20 + c)*9;
        wxy[q] = sside ? (w[d*3+0] + w[d*3+1] + w[d*3+2])     // Wy
                       : (w[0*3+d] + w[1*3+d] + w[2*3+d]);    // Wx
    }
    __syncthreads();

    // BN1 apply + relu + pool1 -> m[u][c][x]
    for (int q = tid; q < 2000; q += 256) {
        int u = q / 500, r = q % 500;
        int c = r / 25, x = r % 25;
        float sc = bn[u*20+c], sh = bn[80 + u*20+c];
        float a0 = fs[(u*50 + 2*x  )*21 + c]*sc + sh;
        float a1 = fs[(u*50 + 2*x+1)*21 + c]*sc + sh;
        m[u*500 + c*25 + x] = fmaxf(fmaxf(a0, a1), 0.f);
    }
    __syncthreads();

    // separable conv1d: A[u][o][x] = sum_c sum_d wxy[side][o][c][d] * m[u][c][x+d]
    for (int q = tid; q < 3680; q += 256) {
        int u = q / 920, r = q % 920;
        int o = r / 23, x = r % 23;
        int side = u >> 1;
        const float* wb = wxy + side*2400 + o*60;
        const float* mb = m + u*500 + x;
        float acc = 0.f;
#pragma unroll
        for (int c = 0; c < 20; c++) {
            const float* w = wb + c*3;
            const float* mm = mb + c*25;
            acc += w[0]*mm[0] + w[1]*mm[1] + w[2]*mm[2];
        }
        as_[q] = acc;
        int b = bp*2 + (u & 1);
        g_A[(size_t)(side*BATCH + b)*920 + r] = acc;
    }
    __syncthreads();

    // per-sample sums for BN2 stats, layout [o][side][b]
    if (tid < 160) {
        int u = tid / 40, o = tid % 40;
        int side = u >> 1;
        int b = bp*2 + (u & 1);
        float s = 0.f, s2 = 0.f;
#pragma unroll
        for (int x = 0; x < 23; x++) {
            float v = as_[u*920 + o*23 + x];
            s += v; s2 += v*v;
        }
        g_s1[o*(2*BATCH) + side*BATCH + b] = s;
        g_s2[o*(2*BATCH) + side*BATCH + b] = s2;
    }
}

// ---------------------------------------------------------------------------
// k3: blocks 0-39 -> BN2 global stats; blocks 40-58 -> weff = Wfc2 @ Wfc1
// ---------------------------------------------------------------------------
__global__ void k3(const float* __restrict__ g2, const float* __restrict__ beta2,
                   const float* __restrict__ Wfc1, const float* __restrict__ Wfc2,
                   const float* __restrict__ bfc1, const float* __restrict__ bfc2)
{
    const int blk = blockIdx.x, tid = threadIdx.x;
    if (blk < 40) {
        const int o = blk;
        __shared__ double rS[256], rQ[256];
        double aS = 0.0, aQ = 0.0;
        for (int b = tid; b < BATCH; b += 256) {
            double sA = g_s1[o*1024 + b],       sB = g_s1[o*1024 + 512 + b];
            double qA = g_s2[o*1024 + b],       qB = g_s2[o*1024 + 512 + b];
            aS += 23.0*(sA + sB);
            aQ += 23.0*qA + 23.0*qB + 2.0*sA*sB;
        }
        rS[tid] = aS; rQ[tid] = aQ;
        __syncthreads();
        for (int s = 128; s > 0; s >>= 1) {
            if (tid < s) { rS[tid] += rS[tid+s]; rQ[tid] += rQ[tid+s]; }
            __syncthreads();
        }
        if (tid == 0) {
            double N    = (double)BATCH * 529.0;
            double mean = rS[0] / N;
            double var  = rQ[0] / N - mean*mean;
            float  sc   = g2[o] * (float)(1.0 / sqrt(var + (double)EPSV));
            g_bn2[o]      = sc;
            g_bn2[C2 + o] = beta2[o] - (float)mean * sc;
        }
    } else {
        int k = (blk - 40)*256 + tid;
        if (k < 4840) {
            float w = 0.f;
#pragma unroll
            for (int c = 0; c < 20; c++) w += Wfc2[c]*Wfc1[c*4840 + k];
            g_weff[k] = w;
        }
        if (blk == 40 && tid == 0) {
            float z = bfc2[0];
#pragma unroll
            for (int c = 0; c < 20; c++) z += Wfc2[c]*bfc1[c];
            g_bias0 = z;
        }
    }
}

// ---------------------------------------------------------------------------
// kF: per sample — BN2 apply + pool2 + relu + dot(weff) + sigmoid
// ---------------------------------------------------------------------------
__global__ __launch_bounds__(256)
void kF(float* __restrict__ out)
{
    __shared__ float ua[440], vb[440], sh_s[40], red[256];
    const int b = blockIdx.x, tid = threadIdx.x;

    for (int q = tid; q < 880; q += 256) {
        int half = (q >= 440);
        int r = q - half*440;
        int o = r / 11, xx = r % 11;
        float sc = g_bn2[o];
        const float* p = &g_A[(size_t)(half*BATCH + b)*920 + o*23];
        float v = fmaxf(sc*p[2*xx], sc*p[2*xx+1]);
        (half ? vb : ua)[r] = v;
    }
    if (tid < 40) sh_s[tid] = g_bn2[C2 + tid];
    __syncthreads();

    float part = 0.f;
    for (int q = tid; q < 4840; q += 256) {
        int o = q / 121, r = q % 121, yy = r / 11, xx = r % 11;
        part += g_weff[q] * fmaxf(ua[o*11 + xx] + vb[o*11 + yy] + sh_s[o], 0.f);
    }
    red[tid] = part;
    __syncthreads();
    for (int s = 128; s > 0; s >>= 1) {
        if (tid < s) red[tid] += red[tid+s];
        __syncthreads();
    }
    if (tid == 0) out[b] = 1.f / (1.f + expf(-(red[0] + g_bias0)));
}

// ---------------------------------------------------------------------------
extern "C" void kernel_launch(void* const* d_in, const int* in_sizes, int n_in,
                              void* d_out, int out_size)
{
    const int*   src     = (const int*)  d_in[0];
    const int*   trg     = (const int*)  d_in[1];
    const float* emb_src = (const float*)d_in[3];
    const float* emb_trg = (const float*)d_in[4];
    const float* W1      = (const float*)d_in[5];
    const float* g1      = (const float*)d_in[7];
    const float* beta1   = (const float*)d_in[8];
    const float* W2      = (const float*)d_in[9];
    const float* g2      = (const float*)d_in[11];
    const float* beta2   = (const float*)d_in[12];
    const float* Wfc1    = (const float*)d_in[13];
    const float* bfc1    = (const float*)d_in[14];
    const float* Wfc2    = (const float*)d_in[15];
    const float* bfc2    = (const float*)d_in[16];

    cudaFuncSetAttribute(k1, cudaFuncAttributeMaxDynamicSharedMemorySize, SMEM_K1);

    k1<<<BATCH/2, 256, SMEM_K1>>>(src, trg, emb_src, emb_trg, W1, g1, beta1, W2);
    k3<<<59, 256>>>(g2, beta2, Wfc1, Wfc2, bfc1, bfc2);
    kF<<<BATCH, 256>>>((float*)d_out);
}